// round 3
// baseline (speedup 1.0000x reference)
#include <cuda_runtime.h>
#include <math.h>

#define BB   4
#define HH   128
#define WWd  128
#define DIM  128
#define C2   64
#define NHh  8
#define NREG 256
#define W2   64
#define LL   16384
#define SCALE 0.08838834764831845f   // 128^-0.5

// ---------------- scratch (device globals; no allocation allowed) ----------
__device__ float g_winv[BB*NREG*W2*C2];   // window V (lcev1 source), (b,r,t,c)
__device__ float g_qb  [BB*NREG*W2*C2];   // bra q, (b,r,t,c)
__device__ float g_kb  [BB*NREG*W2*C2];
__device__ float g_vb  [BB*NREG*W2*C2];
__device__ float g_qr  [BB*NREG*C2];      // pooled q, (b,r,c)
__device__ float g_kr  [BB*NREG*C2];      // pooled k, (b,r,c)
__device__ int   g_idx [BB*NREG*4];
__device__ float g_mid [(size_t)BB*LL*DIM];       // token-major "out" pre-CA
__device__ float g_cq  [(size_t)BB*DIM*LL];       // (b*128 + h*16+d, l)
__device__ float g_ck  [(size_t)BB*DIM*LL];
__device__ float g_cv  [(size_t)BB*LL*DIM];       // token-major
__device__ float g_invn[2*BB*DIM];                // [0..511]=q rows, [512..1023]=k rows
__device__ float g_attn[BB*NHh*16*16];

// ---------------- kA: window QKV + window attention ------------------------
__global__ void kA_win(const float* __restrict__ x, const float* __restrict__ w,
                       const float* __restrict__ bias) {
    extern __shared__ float sm[];
    float* s_wx  = sm;          // 64*64
    float* s_qkv = sm + 4096;   // 64*192
    int wid = blockIdx.x;
    int b = wid >> 8, r = wid & 255, ry = r >> 4, rx = r & 15;
    int tid = threadIdx.x;

    for (int i = tid; i < 4096; i += 256) {
        int t = i >> 6, c = i & 63;
        int y = ry*8 + (t >> 3), xx = rx*8 + (t & 7);
        s_wx[i] = x[(((size_t)b*HH + y)*WWd + xx)*DIM + c];
    }
    __syncthreads();
    for (int i = tid; i < 64*192; i += 256) {
        int t = i / 192, j = i - t*192;
        float acc = bias[j];
        const float* wr = s_wx + t*64;
        #pragma unroll 8
        for (int c = 0; c < 64; c++) acc += wr[c] * w[c*192 + j];
        s_qkv[i] = acc;
    }
    __syncthreads();
    size_t base = (size_t)wid * 4096;
    for (int i = tid; i < 4096; i += 256) {
        int t = i >> 6, c = i & 63;
        g_winv[base + i] = s_qkv[t*192 + 128 + c];
    }
    // 8 heads x 64 queries, online softmax over 64 keys (hdh = 8)
    for (int p = tid; p < 512; p += 256) {
        int h = p >> 6, qi = p & 63;
        float qv[8];
        #pragma unroll
        for (int d = 0; d < 8; d++) qv[d] = s_qkv[qi*192 + h*8 + d] * SCALE;
        float m = -INFINITY, ssum = 0.f, acc[8];
        #pragma unroll
        for (int d = 0; d < 8; d++) acc[d] = 0.f;
        for (int j = 0; j < 64; j++) {
            const float* kr = s_qkv + j*192 + 64 + h*8;
            float s = 0.f;
            #pragma unroll
            for (int d = 0; d < 8; d++) s += qv[d]*kr[d];
            float nm = fmaxf(m, s);
            float corr = __expf(m - nm);
            float e = __expf(s - nm);
            ssum = ssum*corr + e;
            const float* vr = s_qkv + j*192 + 128 + h*8;
            #pragma unroll
            for (int d = 0; d < 8; d++) acc[d] = acc[d]*corr + e*vr[d];
            m = nm;
        }
        int y = ry*8 + (qi >> 3), xx = rx*8 + (qi & 7);
        size_t mo = ((size_t)b*LL + y*WWd + xx)*DIM + h*8;
        float inv = 1.f/ssum;
        #pragma unroll
        for (int d = 0; d < 8; d++) g_mid[mo + d] = acc[d]*inv;
    }
}

// ---------------- kB: BRA QKV (region-major) + window pooling --------------
__global__ void kB_bra(const float* __restrict__ x, const float* __restrict__ w,
                       const float* __restrict__ bias) {
    extern __shared__ float sm[];
    float* s_wx  = sm;
    float* s_qkv = sm + 4096;
    int wid = blockIdx.x;
    int b = wid >> 8, r = wid & 255, ry = r >> 4, rx = r & 15;
    int tid = threadIdx.x;

    for (int i = tid; i < 4096; i += 256) {
        int t = i >> 6, c = i & 63;
        int y = ry*8 + (t >> 3), xx = rx*8 + (t & 7);
        s_wx[i] = x[(((size_t)b*HH + y)*WWd + xx)*DIM + 64 + c];
    }
    __syncthreads();
    for (int i = tid; i < 64*192; i += 256) {
        int t = i / 192, j = i - t*192;
        float acc = bias[j];
        const float* wr = s_wx + t*64;
        #pragma unroll 8
        for (int c = 0; c < 64; c++) acc += wr[c] * w[c*192 + j];
        s_qkv[i] = acc;
    }
    __syncthreads();
    size_t base = (size_t)wid * 4096;
    for (int i = tid; i < 4096; i += 256) {
        int t = i >> 6, c = i & 63;
        g_qb[base + i] = s_qkv[t*192 + c];
        g_kb[base + i] = s_qkv[t*192 + 64 + c];
        g_vb[base + i] = s_qkv[t*192 + 128 + c];
    }
    if (tid < 64) {
        float sq = 0.f, sk = 0.f;
        for (int t = 0; t < 64; t++) {
            sq += s_qkv[t*192 + tid];
            sk += s_qkv[t*192 + 64 + tid];
        }
        g_qr[(wid)*64 + tid] = sq * 0.015625f;
        g_kr[(wid)*64 + tid] = sk * 0.015625f;
    }
}

// ---------------- kC: routing scores + top-4 --------------------------------
__global__ void kC_route() {
    __shared__ float s_q[64];
    __shared__ float s_a[256];
    int b = blockIdx.x >> 8, i = blockIdx.x & 255;
    int tid = threadIdx.x;
    if (tid < 64) s_q[tid] = g_qr[(b*256 + i)*64 + tid];
    __syncthreads();
    const float* kr = g_kr + (size_t)(b*256 + tid)*64;
    float a = 0.f;
    #pragma unroll 8
    for (int c = 0; c < 64; c++) a += s_q[c]*kr[c];
    s_a[tid] = a;
    __syncthreads();
    if (tid == 0) {
        for (int s = 0; s < 4; s++) {
            float best = -INFINITY; int bj = 0;
            for (int j = 0; j < 256; j++)
                if (s_a[j] > best) { best = s_a[j]; bj = j; }
            g_idx[(b*256 + i)*4 + s] = bj;
            s_a[bj] = -INFINITY;
        }
    }
}

// ---------------- kD: BRA gathered attention --------------------------------
__global__ void kD_attn() {
    __shared__ float s_k[256*8];
    __shared__ float s_v[256*8];
    __shared__ int   s_i4[4];
    int id = blockIdx.x;
    int b = id >> 11, h = (id >> 8) & 7, r = id & 255;
    int tid = threadIdx.x;  // 64 threads
    if (tid < 4) s_i4[tid] = g_idx[(b*256 + r)*4 + tid];
    __syncthreads();
    for (int i = tid; i < 2048; i += 64) {
        int key = i >> 3, d = i & 7;
        int reg = s_i4[key >> 6], t = key & 63;
        size_t off = (((size_t)(b*256 + reg))*64 + t)*64 + h*8 + d;
        s_k[i] = g_kb[off];
        s_v[i] = g_vb[off];
    }
    __syncthreads();
    int qi = tid;
    float qv[8];
    size_t qoff = (((size_t)(b*256 + r))*64 + qi)*64 + h*8;
    #pragma unroll
    for (int d = 0; d < 8; d++) qv[d] = g_qb[qoff + d] * SCALE;
    float m = -INFINITY, ssum = 0.f, acc[8];
    #pragma unroll
    for (int d = 0; d < 8; d++) acc[d] = 0.f;
    for (int j = 0; j < 256; j++) {
        const float* kp = s_k + j*8;
        float s = 0.f;
        #pragma unroll
        for (int d = 0; d < 8; d++) s += qv[d]*kp[d];
        float nm = fmaxf(m, s);
        float corr = __expf(m - nm);
        float e = __expf(s - nm);
        ssum = ssum*corr + e;
        const float* vp = s_v + j*8;
        #pragma unroll
        for (int d = 0; d < 8; d++) acc[d] = acc[d]*corr + e*vp[d];
        m = nm;
    }
    int y = (r >> 4)*8 + (qi >> 3), xx = (r & 15)*8 + (qi & 7);
    size_t mo = ((size_t)b*LL + y*WWd + xx)*DIM + 64 + h*8;
    float inv = 1.f/ssum;
    #pragma unroll
    for (int d = 0; d < 8; d++) g_mid[mo + d] = acc[d]*inv;
}

// ---------------- kE: depthwise 3x3 LEPE, added into mid --------------------
__global__ void kE_lepe(const float* __restrict__ lw, const float* __restrict__ lb) {
    int pid = blockIdx.x;
    int b = pid >> 14, l = pid & 16383;
    int y = l >> 7, xx = l & 127;
    int c = threadIdx.x;   // 128
    float acc = lb[c];
    const float* wr = lw + c*9;
    #pragma unroll
    for (int ky = 0; ky < 3; ky++) {
        int yy = y + ky - 1;
        if (yy < 0 || yy >= 128) continue;
        #pragma unroll
        for (int kx = 0; kx < 3; kx++) {
            int xc = xx + kx - 1;
            if (xc < 0 || xc >= 128) continue;
            int rr = (yy >> 3)*16 + (xc >> 3), tt = (yy & 7)*8 + (xc & 7);
            size_t off = (((size_t)(b*256 + rr))*64 + tt)*64;
            float v = (c < 64) ? g_vb[off + c] : g_winv[off + c - 64];
            acc += v * wr[ky*3 + kx];
        }
    }
    g_mid[((size_t)b*LL + l)*DIM + c] += acc;
}

// ---------------- kF1: channel-attn qkv GEMM (128 -> 384) -------------------
__global__ void kF1_caqkv(const float* __restrict__ w, const float* __restrict__ bias) {
    __shared__ float row[128];
    int tok = blockIdx.x;
    int tid = threadIdx.x;  // 384
    if (tid < 128) row[tid] = g_mid[(size_t)tok*128 + tid];
    __syncthreads();
    float acc = bias[tid];
    #pragma unroll 8
    for (int c = 0; c < 128; c++) acc += row[c]*w[c*384 + tid];
    int b = tok >> 14, l = tok & 16383;
    if (tid < 128)      g_cq[((size_t)b*128 + tid)*LL + l] = acc;
    else if (tid < 256) g_ck[((size_t)b*128 + (tid-128))*LL + l] = acc;
    else                g_cv[(size_t)tok*128 + (tid-256)] = acc;
}

// ---------------- kF2: L2 norms over L ---------------------------------------
__global__ void kF2_norm() {
    __shared__ float red[256];
    int row = blockIdx.x;   // 0..1023
    const float* p = (row < 512) ? (g_cq + (size_t)row*LL)
                                 : (g_ck + (size_t)(row-512)*LL);
    int tid = threadIdx.x;
    float s = 0.f;
    for (int l = tid; l < LL; l += 256) { float v = p[l]; s += v*v; }
    red[tid] = s; __syncthreads();
    for (int st = 128; st > 0; st >>= 1) {
        if (tid < st) red[tid] += red[tid + st];
        __syncthreads();
    }
    if (tid == 0) g_invn[row] = 1.f / fmaxf(sqrtf(red[0]), 1e-12f);
}

// ---------------- kF3: 16x16 gram + softmax per (b,h) -----------------------
__global__ void kF3_gram(const float* __restrict__ temp) {
    __shared__ float qs[16*257];
    __shared__ float ks[16*257];
    __shared__ float smm[256];
    int bh = blockIdx.x;
    int b = bh >> 3, h = bh & 7;
    int tid = threadIdx.x;
    int d = tid >> 4, e = tid & 15;
    int rowq = b*128 + h*16;
    float acc = 0.f;
    for (int l0 = 0; l0 < LL; l0 += 256) {
        for (int i = tid; i < 4096; i += 256) {
            int rr = i >> 8, cc = i & 255;
            qs[rr*257 + cc] = g_cq[((size_t)rowq + rr)*LL + l0 + cc];
            ks[rr*257 + cc] = g_ck[((size_t)rowq + rr)*LL + l0 + cc];
        }
        __syncthreads();
        const float* qp = qs + d*257;
        const float* kp = ks + e*257;
        #pragma unroll 8
        for (int c = 0; c < 256; c++) acc += qp[c]*kp[c];
        __syncthreads();
    }
    float val = acc * g_invn[rowq + d] * g_invn[512 + rowq + e] * temp[h];
    smm[tid] = val;
    __syncthreads();
    if (tid < 16) {
        float mx = -INFINITY;
        for (int j = 0; j < 16; j++) mx = fmaxf(mx, smm[tid*16 + j]);
        float ssum = 0.f, ex[16];
        for (int j = 0; j < 16; j++) { ex[j] = __expf(smm[tid*16 + j] - mx); ssum += ex[j]; }
        float inv = 1.f/ssum;
        for (int j = 0; j < 16; j++) g_attn[bh*256 + tid*16 + j] = ex[j]*inv;
    }
}

// ---------------- kF4: cout (16-mix) + 128x128 projection -------------------
__global__ void kF4_out(const float* __restrict__ pw, const float* __restrict__ pb,
                        float* __restrict__ out) {
    __shared__ float s_attn[2048];
    __shared__ float s_cv[32*128];
    __shared__ float s_cout[32*128];
    int tok0 = blockIdx.x * 32;
    int b = tok0 >> 14;
    int tid = threadIdx.x;  // 128
    for (int i = tid; i < 2048; i += 128) s_attn[i] = g_attn[b*2048 + i];
    for (int i = tid; i < 4096; i += 128) s_cv[i] = g_cv[(size_t)tok0*128 + i];
    __syncthreads();
    int h = tid >> 4, d = tid & 15;
    float ar[16];
    #pragma unroll
    for (int e = 0; e < 16; e++) ar[e] = s_attn[h*256 + d*16 + e];
    for (int t = 0; t < 32; t++) {
        const float* cvp = s_cv + t*128 + h*16;
        float s = 0.f;
        #pragma unroll
        for (int e = 0; e < 16; e++) s += ar[e]*cvp[e];
        s_cout[t*128 + tid] = s;
    }
    __syncthreads();
    float bj = pb[tid];
    for (int t = 0; t < 32; t++) {
        float acc = bj;
        const float* cr = s_cout + t*128;
        #pragma unroll 8
        for (int k = 0; k < 128; k++) acc += cr[k]*pw[k*128 + tid];
        out[((size_t)tok0 + t)*128 + tid] = acc;
    }
}

// ---------------- launch -----------------------------------------------------
extern "C" void kernel_launch(void* const* d_in, const int* in_sizes, int n_in,
                              void* d_out, int out_size) {
    const float* x         = (const float*)d_in[0];
    const float* wqkv_w    = (const float*)d_in[1];
    const float* wqkv_b    = (const float*)d_in[2];
    const float* bqkv_w    = (const float*)d_in[3];
    const float* bqkv_b    = (const float*)d_in[4];
    const float* lepe_w    = (const float*)d_in[5];
    const float* lepe_b    = (const float*)d_in[6];
    const float* ca_qkv_w  = (const float*)d_in[7];
    const float* ca_qkv_b  = (const float*)d_in[8];
    const float* ca_temp   = (const float*)d_in[9];
    const float* ca_proj_w = (const float*)d_in[10];
    const float* ca_proj_b = (const float*)d_in[11];
    float* out = (float*)d_out;

    cudaFuncSetAttribute(kA_win, cudaFuncAttributeMaxDynamicSharedMemorySize, 65536);
    cudaFuncSetAttribute(kB_bra, cudaFuncAttributeMaxDynamicSharedMemorySize, 65536);

    kA_win  <<<1024, 256, 65536>>>(x, wqkv_w, wqkv_b);
    kB_bra  <<<1024, 256, 65536>>>(x, bqkv_w, bqkv_b);
    kC_route<<<1024, 256>>>();
    kD_attn <<<8192, 64>>>();
    kE_lepe <<<65536, 128>>>(lepe_w, lepe_b);
    kF1_caqkv<<<65536, 384>>>(ca_qkv_w, ca_qkv_b);
    kF2_norm<<<1024, 256>>>();
    kF3_gram<<<32, 256>>>(ca_temp);
    kF4_out <<<2048, 128>>>(ca_proj_w, ca_proj_b, out);
}

// round 4
// speedup vs baseline: 2.7080x; 2.7080x over previous
#include <cuda_runtime.h>
#include <math.h>

#define BB   4
#define LL   16384
#define SCALE 0.08838834764831845f   // 128^-0.5

// ---------------- scratch ----------------------------------------------------
__device__ __align__(16) float g_winv[BB*256*64*64];   // (b,r,t,c) window V
__device__ __align__(16) float g_qb  [BB*8*256*64*8];  // (b,h,r,t,d) bra q
__device__ __align__(16) float g_kb  [BB*8*256*64*8];
__device__ __align__(16) float g_vb  [BB*8*256*64*8];
__device__ __align__(16) float g_qr  [BB*256*64];
__device__ __align__(16) float g_kr  [BB*256*64];
__device__ int   g_idx [BB*256*4];
__device__ __align__(16) float g_mid [(size_t)BB*LL*128];   // token-major pre-CA
__device__ __align__(16) float g_cq  [(size_t)BB*128*LL];   // (b*128+ch, l)
__device__ __align__(16) float g_ck  [(size_t)BB*128*LL];
__device__ __align__(16) float g_cv  [(size_t)BB*LL*128];   // token-major
__device__ float g_invn[2*BB*128];
__device__ float g_gram[32*256];
__device__ float g_attn[32*256];

// ---------------- kA: window QKV GEMM + window attention --------------------
__global__ void kA_win(const float* __restrict__ x, const float* __restrict__ w,
                       const float* __restrict__ bias) {
    extern __shared__ float sm[];
    float* s_xT  = sm;            // 64 k x 68 (pad) m
    float* s_w   = sm + 64*68;    // 64 x 192
    float* s_qkv = s_w;           // reused after GEMM: 64 x 192
    int wid = blockIdx.x;
    int b = wid >> 8, r = wid & 255, ry = r >> 4, rx = r & 15;
    int tid = threadIdx.x;

    for (int i = tid; i < 4096; i += 256) {
        int t = i >> 6, c = i & 63;
        int y = ry*8 + (t >> 3), xx = rx*8 + (t & 7);
        s_xT[c*68 + t] = x[(((size_t)b*128 + y)*128 + xx)*128 + c];
    }
    for (int i = tid; i < 12288; i += 256) s_w[i] = w[i];
    __syncthreads();

    // GEMM: 64(t) x 192(n) x 64(k); thread tile 4x12
    int t_m = tid & 15, t_n = tid >> 4;
    float acc[4][12];
    #pragma unroll
    for (int i = 0; i < 4; i++)
        #pragma unroll
        for (int j = 0; j < 12; j++) acc[i][j] = 0.f;
    for (int k = 0; k < 64; k++) {
        float4 a4 = *(const float4*)(s_xT + k*68 + t_m*4);
        float av[4] = {a4.x, a4.y, a4.z, a4.w};
        float4 b0 = *(const float4*)(s_w + k*192 + t_n*12);
        float4 b1 = *(const float4*)(s_w + k*192 + t_n*12 + 4);
        float4 b2 = *(const float4*)(s_w + k*192 + t_n*12 + 8);
        float bv[12] = {b0.x,b0.y,b0.z,b0.w,b1.x,b1.y,b1.z,b1.w,b2.x,b2.y,b2.z,b2.w};
        #pragma unroll
        for (int i = 0; i < 4; i++)
            #pragma unroll
            for (int j = 0; j < 12; j++) acc[i][j] += av[i]*bv[j];
    }
    __syncthreads();
    #pragma unroll
    for (int i = 0; i < 4; i++)
        #pragma unroll
        for (int j = 0; j < 12; j++)
            s_qkv[(t_m*4+i)*192 + t_n*12 + j] = acc[i][j] + __ldg(bias + t_n*12 + j);
    __syncthreads();

    size_t base = (size_t)wid * 4096;
    for (int i = tid; i < 4096; i += 256) {
        int t = i >> 6, c = i & 63;
        g_winv[base + i] = s_qkv[t*192 + 128 + c];
    }

    // attention: warp = head, 2 q-rows per thread, no-max softmax
    int h = tid >> 5, lane = tid & 31;
    const float* qp0 = s_qkv + lane*192 + h*8;
    const float* qp1 = s_qkv + (lane+32)*192 + h*8;
    float4 q0a = *(const float4*)qp0, q0b = *(const float4*)(qp0+4);
    float4 q1a = *(const float4*)qp1, q1b = *(const float4*)(qp1+4);
    q0a.x*=SCALE;q0a.y*=SCALE;q0a.z*=SCALE;q0a.w*=SCALE;
    q0b.x*=SCALE;q0b.y*=SCALE;q0b.z*=SCALE;q0b.w*=SCALE;
    q1a.x*=SCALE;q1a.y*=SCALE;q1a.z*=SCALE;q1a.w*=SCALE;
    q1b.x*=SCALE;q1b.y*=SCALE;q1b.z*=SCALE;q1b.w*=SCALE;
    float ssum0 = 0.f, ssum1 = 0.f;
    float4 a0a = {0,0,0,0}, a0b = {0,0,0,0}, a1a = {0,0,0,0}, a1b = {0,0,0,0};
    for (int j = 0; j < 64; j++) {
        const float* kp = s_qkv + j*192 + 64 + h*8;
        const float* vp = s_qkv + j*192 + 128 + h*8;
        float4 ka = *(const float4*)kp, kb4 = *(const float4*)(kp+4);
        float s0 = q0a.x*ka.x + q0a.y*ka.y + q0a.z*ka.z + q0a.w*ka.w
                 + q0b.x*kb4.x + q0b.y*kb4.y + q0b.z*kb4.z + q0b.w*kb4.w;
        float s1 = q1a.x*ka.x + q1a.y*ka.y + q1a.z*ka.z + q1a.w*ka.w
                 + q1b.x*kb4.x + q1b.y*kb4.y + q1b.z*kb4.z + q1b.w*kb4.w;
        float e0 = __expf(s0), e1 = __expf(s1);
        ssum0 += e0; ssum1 += e1;
        float4 va = *(const float4*)vp, vb4 = *(const float4*)(vp+4);
        a0a.x += e0*va.x; a0a.y += e0*va.y; a0a.z += e0*va.z; a0a.w += e0*va.w;
        a0b.x += e0*vb4.x; a0b.y += e0*vb4.y; a0b.z += e0*vb4.z; a0b.w += e0*vb4.w;
        a1a.x += e1*va.x; a1a.y += e1*va.y; a1a.z += e1*va.z; a1a.w += e1*va.w;
        a1b.x += e1*vb4.x; a1b.y += e1*vb4.y; a1b.z += e1*vb4.z; a1b.w += e1*vb4.w;
    }
    float i0 = 1.f/ssum0, i1 = 1.f/ssum1;
    a0a.x*=i0;a0a.y*=i0;a0a.z*=i0;a0a.w*=i0; a0b.x*=i0;a0b.y*=i0;a0b.z*=i0;a0b.w*=i0;
    a1a.x*=i1;a1a.y*=i1;a1a.z*=i1;a1a.w*=i1; a1b.x*=i1;a1b.y*=i1;a1b.z*=i1;a1b.w*=i1;
    {
        int row = lane;
        int y = ry*8 + (row>>3), xx = rx*8 + (row&7);
        float* mo = g_mid + ((size_t)b*LL + y*128 + xx)*128 + h*8;
        *(float4*)mo = a0a; *(float4*)(mo+4) = a0b;
        row = lane + 32;
        y = ry*8 + (row>>3); xx = rx*8 + (row&7);
        mo = g_mid + ((size_t)b*LL + y*128 + xx)*128 + h*8;
        *(float4*)mo = a1a; *(float4*)(mo+4) = a1b;
    }
}

// ---------------- kB: BRA QKV GEMM (head-major out) + pooling ---------------
__global__ void kB_bra(const float* __restrict__ x, const float* __restrict__ w,
                       const float* __restrict__ bias) {
    extern __shared__ float sm[];
    float* s_xT  = sm;
    float* s_w   = sm + 64*68;
    float* s_qkv = s_w;
    int wid = blockIdx.x;
    int b = wid >> 8, r = wid & 255, ry = r >> 4, rx = r & 15;
    int tid = threadIdx.x;

    for (int i = tid; i < 4096; i += 256) {
        int t = i >> 6, c = i & 63;
        int y = ry*8 + (t >> 3), xx = rx*8 + (t & 7);
        s_xT[c*68 + t] = x[(((size_t)b*128 + y)*128 + xx)*128 + 64 + c];
    }
    for (int i = tid; i < 12288; i += 256) s_w[i] = w[i];
    __syncthreads();

    int t_m = tid & 15, t_n = tid >> 4;
    float acc[4][12];
    #pragma unroll
    for (int i = 0; i < 4; i++)
        #pragma unroll
        for (int j = 0; j < 12; j++) acc[i][j] = 0.f;
    for (int k = 0; k < 64; k++) {
        float4 a4 = *(const float4*)(s_xT + k*68 + t_m*4);
        float av[4] = {a4.x, a4.y, a4.z, a4.w};
        float4 b0 = *(const float4*)(s_w + k*192 + t_n*12);
        float4 b1 = *(const float4*)(s_w + k*192 + t_n*12 + 4);
        float4 b2 = *(const float4*)(s_w + k*192 + t_n*12 + 8);
        float bv[12] = {b0.x,b0.y,b0.z,b0.w,b1.x,b1.y,b1.z,b1.w,b2.x,b2.y,b2.z,b2.w};
        #pragma unroll
        for (int i = 0; i < 4; i++)
            #pragma unroll
            for (int j = 0; j < 12; j++) acc[i][j] += av[i]*bv[j];
    }
    __syncthreads();
    #pragma unroll
    for (int i = 0; i < 4; i++)
        #pragma unroll
        for (int j = 0; j < 12; j++)
            s_qkv[(t_m*4+i)*192 + t_n*12 + j] = acc[i][j] + __ldg(bias + t_n*12 + j);
    __syncthreads();

    // head-major global writes: off = ((b*8+h)*256 + r)*512 + t*8 + d
    for (int i = tid; i < 4096; i += 256) {
        int hh = i >> 9, rest = i & 511;
        int t = rest >> 3, d = rest & 7;
        size_t off = ((size_t)(b*8 + hh)*256 + r)*512 + rest;
        g_qb[off] = s_qkv[t*192 + hh*8 + d];
        g_kb[off] = s_qkv[t*192 + 64 + hh*8 + d];
        g_vb[off] = s_qkv[t*192 + 128 + hh*8 + d];
    }
    if (tid < 64) {
        float sq = 0.f, sk = 0.f;
        for (int t = 0; t < 64; t++) {
            sq += s_qkv[t*192 + tid];
            sk += s_qkv[t*192 + 64 + tid];
        }
        g_qr[wid*64 + tid] = sq * 0.015625f;
        g_kr[wid*64 + tid] = sk * 0.015625f;
    }
}

// ---------------- kC: routing + top-4 ---------------------------------------
__global__ void kC_route() {
    __shared__ float s_q[64];
    __shared__ float s_a[256];
    int b = blockIdx.x >> 8, i = blockIdx.x & 255;
    int tid = threadIdx.x;
    if (tid < 64) s_q[tid] = g_qr[(b*256 + i)*64 + tid];
    __syncthreads();
    const float* kr = g_kr + (size_t)(b*256 + tid)*64;
    float a = 0.f;
    #pragma unroll 8
    for (int c = 0; c < 64; c++) a += s_q[c]*kr[c];
    s_a[tid] = a;
    __syncthreads();
    if (tid == 0) {
        for (int s = 0; s < 4; s++) {
            float best = -INFINITY; int bj = 0;
            for (int j = 0; j < 256; j++)
                if (s_a[j] > best) { best = s_a[j]; bj = j; }
            g_idx[(b*256 + i)*4 + s] = bj;
            s_a[bj] = -INFINITY;
        }
    }
}

// ---------------- kD: BRA gathered attention (2 heads/block) ----------------
__global__ void kD_attn() {
    __shared__ __align__(16) float s_k[2*256*8];
    __shared__ __align__(16) float s_v[2*256*8];
    __shared__ int s_i4[4];
    int bid = blockIdx.x;                     // 4096: b(4) x hp(4) x r(256)
    int b = bid >> 10, hp = (bid >> 8) & 3, r = bid & 255;
    int tid = threadIdx.x;                    // 128
    if (tid < 4) s_i4[tid] = g_idx[(b*256 + r)*4 + tid];
    __syncthreads();
    for (int i = tid; i < 1024; i += 128) {   // float4 units
        int hl = i >> 9, rem = i & 511;
        int key = rem >> 1, d4 = rem & 1;
        int reg = s_i4[key >> 6], t = key & 63;
        size_t off = ((size_t)(b*8 + hp*2 + hl)*256 + reg)*512 + t*8 + d4*4;
        *(float4*)(s_k + i*4) = *(const float4*)(g_kb + off);
        *(float4*)(s_v + i*4) = *(const float4*)(g_vb + off);
    }
    __syncthreads();
    int hl = tid >> 6, row = tid & 63;
    int h = hp*2 + hl;
    size_t qoff = ((size_t)(b*8 + h)*256 + r)*512 + row*8;
    float4 qa = *(const float4*)(g_qb + qoff);
    float4 qb4 = *(const float4*)(g_qb + qoff + 4);
    qa.x*=SCALE;qa.y*=SCALE;qa.z*=SCALE;qa.w*=SCALE;
    qb4.x*=SCALE;qb4.y*=SCALE;qb4.z*=SCALE;qb4.w*=SCALE;
    const float* kbase = s_k + hl*2048;
    const float* vbase = s_v + hl*2048;
    float ssum = 0.f;
    float4 aa = {0,0,0,0}, ab = {0,0,0,0};
    for (int j = 0; j < 256; j++) {
        float4 ka = *(const float4*)(kbase + j*8);
        float4 kb4 = *(const float4*)(kbase + j*8 + 4);
        float s = qa.x*ka.x + qa.y*ka.y + qa.z*ka.z + qa.w*ka.w
                + qb4.x*kb4.x + qb4.y*kb4.y + qb4.z*kb4.z + qb4.w*kb4.w;
        float e = __expf(s);
        ssum += e;
        float4 va = *(const float4*)(vbase + j*8);
        float4 vb4 = *(const float4*)(vbase + j*8 + 4);
        aa.x += e*va.x; aa.y += e*va.y; aa.z += e*va.z; aa.w += e*va.w;
        ab.x += e*vb4.x; ab.y += e*vb4.y; ab.z += e*vb4.z; ab.w += e*vb4.w;
    }
    float inv = 1.f/ssum;
    aa.x*=inv;aa.y*=inv;aa.z*=inv;aa.w*=inv;
    ab.x*=inv;ab.y*=inv;ab.z*=inv;ab.w*=inv;
    int y = (r >> 4)*8 + (row >> 3), xx = (r & 15)*8 + (row & 7);
    float* mo = g_mid + ((size_t)b*LL + y*128 + xx)*128 + 64 + h*8;
    *(float4*)mo = aa; *(float4*)(mo+4) = ab;
}

// ---------------- kE: depthwise 3x3 LEPE ------------------------------------
__global__ void kE_lepe(const float* __restrict__ lw, const float* __restrict__ lb) {
    int pid = blockIdx.x*2 + (threadIdx.x >> 7);
    int b = pid >> 14, l = pid & 16383;
    int y = l >> 7, xx = l & 127;
    int c = threadIdx.x & 127;
    float acc = __ldg(lb + c);
    const float* wr = lw + c*9;
    #pragma unroll
    for (int ky = 0; ky < 3; ky++) {
        int yy = y + ky - 1;
        if (yy < 0 || yy >= 128) continue;
        #pragma unroll
        for (int kx = 0; kx < 3; kx++) {
            int xc = xx + kx - 1;
            if (xc < 0 || xc >= 128) continue;
            int rr = (yy >> 3)*16 + (xc >> 3), tt = (yy & 7)*8 + (xc & 7);
            float v;
            if (c < 64) {
                int hh = c >> 3, d = c & 7;
                v = g_vb[((size_t)(b*8 + hh)*256 + rr)*512 + tt*8 + d];
            } else {
                v = g_winv[((size_t)(b*256 + rr))*4096 + tt*64 + (c - 64)];
            }
            acc += v * __ldg(wr + ky*3 + kx);
        }
    }
    g_mid[((size_t)b*LL + l)*128 + c] += acc;
}

// ---------------- kF1: CA-qkv GEMM 65536x384x128 -----------------------------
__global__ void kF1_caqkv(const float* __restrict__ w, const float* __restrict__ bias) {
    extern __shared__ float sm[];
    float* AsT = sm;          // 128 k x 68 (pad) m
    float* Bs  = sm + 8704;   // 128 k x 128 n
    float* Cs  = sm;          // reuse AsT region for epilogue staging
    int m0 = blockIdx.x * 64;
    int nb = blockIdx.y;      // 0:q 1:k 2:v
    int tid = threadIdx.x;

    for (int i = tid; i < 8192; i += 256) {
        int t = i >> 7, k = i & 127;
        AsT[k*68 + t] = g_mid[(size_t)(m0 + t)*128 + k];
    }
    for (int i = tid; i < 16384; i += 256) {
        int k = i >> 7, n = i & 127;
        Bs[i] = w[k*384 + nb*128 + n];
    }
    __syncthreads();

    int t_m = tid & 15, t_n = tid >> 4;   // m=t_m*4, n=t_n*8
    float acc[4][8];
    #pragma unroll
    for (int i = 0; i < 4; i++)
        #pragma unroll
        for (int j = 0; j < 8; j++) acc[i][j] = 0.f;
    #pragma unroll 4
    for (int k = 0; k < 128; k++) {
        float4 a4 = *(const float4*)(AsT + k*68 + t_m*4);
        float av[4] = {a4.x, a4.y, a4.z, a4.w};
        float4 b0 = *(const float4*)(Bs + k*128 + t_n*8);
        float4 b1 = *(const float4*)(Bs + k*128 + t_n*8 + 4);
        float bv[8] = {b0.x,b0.y,b0.z,b0.w,b1.x,b1.y,b1.z,b1.w};
        #pragma unroll
        for (int i = 0; i < 4; i++)
            #pragma unroll
            for (int j = 0; j < 8; j++) acc[i][j] += av[i]*bv[j];
    }
    __syncthreads();

    int b = m0 >> 14, l0 = m0 & 16383;
    if (nb < 2) {
        // stage transposed: Cs[n*68 + m]
        #pragma unroll
        for (int i = 0; i < 4; i++)
            #pragma unroll
            for (int j = 0; j < 8; j++)
                Cs[(t_n*8 + j)*68 + t_m*4 + i] = acc[i][j] + __ldg(bias + nb*128 + t_n*8 + j);
        __syncthreads();
        float* dst = nb ? g_ck : g_cq;
        for (int i = tid; i < 8192; i += 256) {
            int n = i >> 6, m = i & 63;
            dst[((size_t)b*128 + n)*16384 + l0 + m] = Cs[n*68 + m];
        }
    } else {
        // stage token-major: Cs[m*132 + n]
        #pragma unroll
        for (int i = 0; i < 4; i++)
            #pragma unroll
            for (int j = 0; j < 8; j++)
                Cs[(t_m*4 + i)*132 + t_n*8 + j] = acc[i][j] + __ldg(bias + 256 + t_n*8 + j);
        __syncthreads();
        for (int i = tid; i < 8192; i += 256) {
            int m = i >> 7, n = i & 127;
            g_cv[(size_t)(m0 + m)*128 + n] = Cs[m*132 + n];
        }
    }
}

// ---------------- kF2: L2 norms + gram zeroing --------------------------------
__global__ void kF2_norm() {
    __shared__ float red[256];
    int row = blockIdx.x;
    int tid = threadIdx.x;
    if (row < 32) g_gram[row*256 + tid] = 0.f;
    const float* p = (row < 512) ? (g_cq + (size_t)row*16384)
                                 : (g_ck + (size_t)(row-512)*16384);
    const float4* p4 = (const float4*)p;
    float s = 0.f;
    for (int l = tid; l < 4096; l += 256) {
        float4 v = p4[l];
        s += v.x*v.x + v.y*v.y + v.z*v.z + v.w*v.w;
    }
    red[tid] = s; __syncthreads();
    for (int st = 128; st > 0; st >>= 1) {
        if (tid < st) red[tid] += red[tid + st];
        __syncthreads();
    }
    if (tid == 0) g_invn[row] = 1.f / fmaxf(sqrtf(red[0]), 1e-12f);
}

// ---------------- kF3: partial 16x16 grams (L split over 64 chunks) ----------
__global__ void kF3_gram() {
    __shared__ __align__(16) float qs[16*260];
    __shared__ __align__(16) float ks[16*260];
    int bid = blockIdx.x;          // 2048: bh(32) x chunk(64)
    int bh = bid >> 6, ch = bid & 63;
    int b = bh >> 3, h = bh & 7;
    int rowq = b*128 + h*16;
    int l0 = ch*256;
    int tid = threadIdx.x;
    for (int i = tid; i < 4096; i += 256) {
        int rr = i >> 8, cc = i & 255;
        qs[rr*260 + cc] = g_cq[((size_t)rowq + rr)*16384 + l0 + cc];
        ks[rr*260 + cc] = g_ck[((size_t)rowq + rr)*16384 + l0 + cc];
    }
    __syncthreads();
    int d = tid >> 4, e = tid & 15;
    const float4* qp = (const float4*)(qs + d*260);
    const float4* kp = (const float4*)(ks + e*260);
    float acc = 0.f;
    #pragma unroll 8
    for (int c = 0; c < 64; c++) {
        float4 a = qp[c], bv = kp[c];
        acc += a.x*bv.x + a.y*bv.y + a.z*bv.z + a.w*bv.w;
    }
    atomicAdd(&g_gram[bh*256 + tid], acc);
}

// ---------------- kF3b: normalize + softmax -----------------------------------
__global__ void kF3b(const float* __restrict__ temp) {
    __shared__ float smm[256];
    int bh = blockIdx.x;
    int b = bh >> 3, h = bh & 7;
    int tid = threadIdx.x;
    int d = tid >> 4, e = tid & 15;
    int rowq = b*128 + h*16;
    smm[tid] = g_gram[bh*256 + tid] * g_invn[rowq + d] * g_invn[512 + rowq + e]
             * __ldg(temp + h);
    __syncthreads();
    if (tid < 16) {
        float mx = -INFINITY;
        for (int j = 0; j < 16; j++) mx = fmaxf(mx, smm[tid*16 + j]);
        float ssum = 0.f, ex[16];
        for (int j = 0; j < 16; j++) { ex[j] = __expf(smm[tid*16 + j] - mx); ssum += ex[j]; }
        float inv = 1.f/ssum;
        for (int j = 0; j < 16; j++) g_attn[bh*256 + tid*16 + j] = ex[j]*inv;
    }
}

// ---------------- kF4: cout mix + 128x128 projection --------------------------
__global__ void kF4_out(const float* __restrict__ pw, const float* __restrict__ pb,
                        float* __restrict__ out) {
    extern __shared__ float sm[];
    float* s_attn = sm;           // 2048
    float* s_cv   = sm + 2048;    // 64 x 128
    float* coutT  = sm + 10240;   // 128 k x 68 (pad) m
    int tok0 = blockIdx.x * 64;
    int b = tok0 >> 14;
    int tid = threadIdx.x;
    for (int i = tid; i < 2048; i += 256) s_attn[i] = g_attn[b*2048 + i];
    for (int i = tid; i < 8192; i += 256) s_cv[i] = g_cv[(size_t)tok0*128 + i];
    __syncthreads();
    // cout[m][ch] = sum_e attn[h][d][e] * cv[m][h*16+e]; ch = h*16+d
    for (int i = tid; i < 8192; i += 256) {
        int m = i >> 7, chn = i & 127;
        int h = chn >> 4;
        const float4* ap = (const float4*)(s_attn + (chn)*16);   // h*256+d*16 == chn*16
        const float4* cvp = (const float4*)(s_cv + m*128 + h*16);
        float4 a0 = ap[0], a1 = ap[1], a2 = ap[2], a3 = ap[3];
        float4 c0 = cvp[0], c1 = cvp[1], c2 = cvp[2], c3 = cvp[3];
        float s = a0.x*c0.x + a0.y*c0.y + a0.z*c0.z + a0.w*c0.w
                + a1.x*c1.x + a1.y*c1.y + a1.z*c1.z + a1.w*c1.w
                + a2.x*c2.x + a2.y*c2.y + a2.z*c2.z + a2.w*c2.w
                + a3.x*c3.x + a3.y*c3.y + a3.z*c3.z + a3.w*c3.w;
        coutT[chn*68 + m] = s;
    }
    __syncthreads();
    // projection: 64(m) x 128(n) x 128(k); A=coutT smem, B=pw global (L1)
    int t_m = tid & 15, t_n = tid >> 4;
    float acc[4][8];
    #pragma unroll
    for (int i = 0; i < 4; i++)
        #pragma unroll
        for (int j = 0; j < 8; j++) acc[i][j] = 0.f;
    #pragma unroll 4
    for (int k = 0; k < 128; k++) {
        float4 a4 = *(const float4*)(coutT + k*68 + t_m*4);
        float av[4] = {a4.x, a4.y, a4.z, a4.w};
        float4 b0 = __ldg((const float4*)(pw + k*128 + t_n*8));
        float4 b1 = __ldg((const float4*)(pw + k*128 + t_n*8 + 4));
        float bv[8] = {b0.x,b0.y,b0.z,b0.w,b1.x,b1.y,b1.z,b1.w};
        #pragma unroll
        for (int i = 0; i < 4; i++)
            #pragma unroll
            for (int j = 0; j < 8; j++) acc[i][j] += av[i]*bv[j];
    }
    float4 pb0 = __ldg((const float4*)(pb + t_n*8));
    float4 pb1 = __ldg((const float4*)(pb + t_n*8 + 4));
    float bb[8] = {pb0.x,pb0.y,pb0.z,pb0.w,pb1.x,pb1.y,pb1.z,pb1.w};
    #pragma unroll
    for (int i = 0; i < 4; i++) {
        float* op = out + ((size_t)tok0 + t_m*4 + i)*128 + t_n*8;
        float4 r0 = {acc[i][0]+bb[0], acc[i][1]+bb[1], acc[i][2]+bb[2], acc[i][3]+bb[3]};
        float4 r1 = {acc[i][4]+bb[4], acc[i][5]+bb[5], acc[i][6]+bb[6], acc[i][7]+bb[7]};
        *(float4*)op = r0; *(float4*)(op+4) = r1;
    }
}

// ---------------- launch ------------------------------------------------------
extern "C" void kernel_launch(void* const* d_in, const int* in_sizes, int n_in,
                              void* d_out, int out_size) {
    const float* x         = (const float*)d_in[0];
    const float* wqkv_w    = (const float*)d_in[1];
    const float* wqkv_b    = (const float*)d_in[2];
    const float* bqkv_w    = (const float*)d_in[3];
    const float* bqkv_b    = (const float*)d_in[4];
    const float* lepe_w    = (const float*)d_in[5];
    const float* lepe_b    = (const float*)d_in[6];
    const float* ca_qkv_w  = (const float*)d_in[7];
    const float* ca_qkv_b  = (const float*)d_in[8];
    const float* ca_temp   = (const float*)d_in[9];
    const float* ca_proj_w = (const float*)d_in[10];
    const float* ca_proj_b = (const float*)d_in[11];
    float* out = (float*)d_out;

    static bool attr_done = false;
    if (!attr_done) {
        cudaFuncSetAttribute(kA_win,   cudaFuncAttributeMaxDynamicSharedMemorySize, 66560);
        cudaFuncSetAttribute(kB_bra,   cudaFuncAttributeMaxDynamicSharedMemorySize, 66560);
        cudaFuncSetAttribute(kF1_caqkv,cudaFuncAttributeMaxDynamicSharedMemorySize, 100352);
        cudaFuncSetAttribute(kF4_out,  cudaFuncAttributeMaxDynamicSharedMemorySize, 75776);
        attr_done = true;
    }

    kA_win   <<<1024, 256, 66560>>>(x, wqkv_w, wqkv_b);
    kB_bra   <<<1024, 256, 66560>>>(x, bqkv_w, bqkv_b);
    kC_route <<<1024, 256>>>();
    kD_attn  <<<4096, 128>>>();
    kE_lepe  <<<32768, 256>>>(lepe_w, lepe_b);
    kF1_caqkv<<<dim3(1024, 3), 256, 100352>>>(ca_qkv_w, ca_qkv_b);
    kF2_norm <<<1024, 256>>>();
    kF3_gram <<<2048, 256>>>();
    kF3b     <<<32, 256>>>(ca_temp);
    kF4_out  <<<1024, 256, 75776>>>(ca_proj_w, ca_proj_b, out);
}

// round 5
// speedup vs baseline: 2.8938x; 1.0686x over previous
#include <cuda_runtime.h>
#include <math.h>

#define BB   4
#define LL   16384
#define SCALE 0.08838834764831845f   // 128^-0.5

typedef unsigned long long ull;

__device__ __forceinline__ ull pk2(float a, float b) {
    ull r; asm("mov.b64 %0,{%1,%2};" : "=l"(r) : "f"(a), "f"(b)); return r;
}
__device__ __forceinline__ ull dup2(float a) { return pk2(a, a); }
__device__ __forceinline__ void up2(ull v, float& a, float& b) {
    asm("mov.b64 {%0,%1},%2;" : "=f"(a), "=f"(b) : "l"(v));
}
__device__ __forceinline__ ull fma2(ull a, ull b, ull c) {
    ull d; asm("fma.rn.f32x2 %0,%1,%2,%3;" : "=l"(d) : "l"(a), "l"(b), "l"(c)); return d;
}
__device__ __forceinline__ ull mul2(ull a, ull b) {
    ull d; asm("mul.rn.f32x2 %0,%1,%2;" : "=l"(d) : "l"(a), "l"(b)); return d;
}
__device__ __forceinline__ float hadd2(ull v) { float a, b; up2(v, a, b); return a + b; }

// ---------------- scratch ----------------------------------------------------
__device__ __align__(16) float g_winv[BB*256*64*64];   // (b,r,t,c) window V
__device__ __align__(16) float g_qb  [BB*8*256*64*8];  // (b,h,r,t,d)
__device__ __align__(16) float g_kb  [BB*8*256*64*8];
__device__ __align__(16) float g_vb  [BB*8*256*64*8];
__device__ __align__(16) float g_qr  [BB*256*64];
__device__ __align__(16) float g_kr  [BB*256*64];
__device__ int   g_idx [BB*256*4];
__device__ __align__(16) float g_mid [(size_t)BB*LL*128];   // token-major pre-CA
__device__ __align__(16) float g_cq  [(size_t)BB*LL*128];   // token-major now
__device__ __align__(16) float g_ck  [(size_t)BB*LL*128];
__device__ __align__(16) float g_cv  [(size_t)BB*LL*128];
__device__ float g_norm2[2*BB*128];                          // sumsq per channel row
__device__ float g_gram[32*256];
__device__ float g_attn[32*256];

// ---------------- kA: window QKV GEMM + window attention --------------------
__global__ void kA_win(const float* __restrict__ x, const float* __restrict__ w,
                       const float* __restrict__ bias) {
    extern __shared__ float sm[];
    float* s_xT  = sm;            // 64 k x 68 m
    float* s_w   = sm + 64*68;    // 64 x 192 (reused as s_qkv)
    float* s_qkv = s_w;
    int wid = blockIdx.x;
    int b = wid >> 8, r = wid & 255, ry = r >> 4, rx = r & 15;
    int tid = threadIdx.x;

    for (int i = tid; i < 4096; i += 256) {
        int t = i >> 6, c = i & 63;
        int y = ry*8 + (t >> 3), xx = rx*8 + (t & 7);
        s_xT[c*68 + t] = x[(((size_t)b*128 + y)*128 + xx)*128 + c];
    }
    for (int i = tid; i < 12288; i += 256) s_w[i] = w[i];
    __syncthreads();

    int t_m = tid & 15, t_n = tid >> 4;     // m = t_m*4, n = t_n*12
    ull acc[4][6];
    #pragma unroll
    for (int i = 0; i < 4; i++)
        #pragma unroll
        for (int j = 0; j < 6; j++) acc[i][j] = 0ull;
    for (int k = 0; k < 64; k++) {
        float4 a4 = *(const float4*)(s_xT + k*68 + t_m*4);
        ull a0 = dup2(a4.x), a1 = dup2(a4.y), a2 = dup2(a4.z), a3 = dup2(a4.w);
        const ull* bp = (const ull*)(s_w + k*192 + t_n*12);
        ull b0=bp[0], b1=bp[1], b2=bp[2], b3=bp[3], b4=bp[4], b5=bp[5];
        acc[0][0]=fma2(a0,b0,acc[0][0]); acc[0][1]=fma2(a0,b1,acc[0][1]);
        acc[0][2]=fma2(a0,b2,acc[0][2]); acc[0][3]=fma2(a0,b3,acc[0][3]);
        acc[0][4]=fma2(a0,b4,acc[0][4]); acc[0][5]=fma2(a0,b5,acc[0][5]);
        acc[1][0]=fma2(a1,b0,acc[1][0]); acc[1][1]=fma2(a1,b1,acc[1][1]);
        acc[1][2]=fma2(a1,b2,acc[1][2]); acc[1][3]=fma2(a1,b3,acc[1][3]);
        acc[1][4]=fma2(a1,b4,acc[1][4]); acc[1][5]=fma2(a1,b5,acc[1][5]);
        acc[2][0]=fma2(a2,b0,acc[2][0]); acc[2][1]=fma2(a2,b1,acc[2][1]);
        acc[2][2]=fma2(a2,b2,acc[2][2]); acc[2][3]=fma2(a2,b3,acc[2][3]);
        acc[2][4]=fma2(a2,b4,acc[2][4]); acc[2][5]=fma2(a2,b5,acc[2][5]);
        acc[3][0]=fma2(a3,b0,acc[3][0]); acc[3][1]=fma2(a3,b1,acc[3][1]);
        acc[3][2]=fma2(a3,b2,acc[3][2]); acc[3][3]=fma2(a3,b3,acc[3][3]);
        acc[3][4]=fma2(a3,b4,acc[3][4]); acc[3][5]=fma2(a3,b5,acc[3][5]);
    }
    __syncthreads();
    {
        float bb[12];
        #pragma unroll
        for (int j = 0; j < 12; j++) bb[j] = __ldg(bias + t_n*12 + j);
        #pragma unroll
        for (int i = 0; i < 4; i++)
            #pragma unroll
            for (int j = 0; j < 6; j++) {
                float lo, hi; up2(acc[i][j], lo, hi);
                s_qkv[(t_m*4+i)*192 + t_n*12 + 2*j]     = lo + bb[2*j];
                s_qkv[(t_m*4+i)*192 + t_n*12 + 2*j + 1] = hi + bb[2*j+1];
            }
    }
    __syncthreads();

    size_t base = (size_t)wid * 4096;
    for (int i = tid; i < 4096; i += 256) {
        int t = i >> 6, c = i & 63;
        g_winv[base + i] = s_qkv[t*192 + 128 + c];
    }

    // attention: warp = head, 2 q-rows per thread
    int h = tid >> 5, lane = tid & 31;
    ull sc = dup2(SCALE);
    const ull* qp0 = (const ull*)(s_qkv + lane*192 + h*8);
    const ull* qp1 = (const ull*)(s_qkv + (lane+32)*192 + h*8);
    ull q0[4], q1[4];
    #pragma unroll
    for (int d = 0; d < 4; d++) { q0[d] = mul2(qp0[d], sc); q1[d] = mul2(qp1[d], sc); }
    float ssum0 = 0.f, ssum1 = 0.f;
    ull a0[4] = {0,0,0,0}, a1[4] = {0,0,0,0};
    #pragma unroll 2
    for (int j = 0; j < 64; j++) {
        const ull* kp = (const ull*)(s_qkv + j*192 + 64 + h*8);
        ull k0=kp[0], k1=kp[1], k2=kp[2], k3=kp[3];
        ull s20 = fma2(q0[0],k0, fma2(q0[1],k1, fma2(q0[2],k2, mul2(q0[3],k3))));
        ull s21 = fma2(q1[0],k0, fma2(q1[1],k1, fma2(q1[2],k2, mul2(q1[3],k3))));
        float e0 = __expf(hadd2(s20));
        float e1 = __expf(hadd2(s21));
        ssum0 += e0; ssum1 += e1;
        ull e0d = dup2(e0), e1d = dup2(e1);
        const ull* vp = (const ull*)(s_qkv + j*192 + 128 + h*8);
        ull v0=vp[0], v1=vp[1], v2=vp[2], v3=vp[3];
        a0[0]=fma2(e0d,v0,a0[0]); a0[1]=fma2(e0d,v1,a0[1]);
        a0[2]=fma2(e0d,v2,a0[2]); a0[3]=fma2(e0d,v3,a0[3]);
        a1[0]=fma2(e1d,v0,a1[0]); a1[1]=fma2(e1d,v1,a1[1]);
        a1[2]=fma2(e1d,v2,a1[2]); a1[3]=fma2(e1d,v3,a1[3]);
    }
    ull i0 = dup2(1.f/ssum0), i1 = dup2(1.f/ssum1);
    {
        int row = lane;
        int y = ry*8 + (row>>3), xx = rx*8 + (row&7);
        ull* mo = (ull*)(g_mid + ((size_t)b*LL + y*128 + xx)*128 + h*8);
        mo[0]=mul2(a0[0],i0); mo[1]=mul2(a0[1],i0); mo[2]=mul2(a0[2],i0); mo[3]=mul2(a0[3],i0);
        row = lane + 32;
        y = ry*8 + (row>>3); xx = rx*8 + (row&7);
        mo = (ull*)(g_mid + ((size_t)b*LL + y*128 + xx)*128 + h*8);
        mo[0]=mul2(a1[0],i1); mo[1]=mul2(a1[1],i1); mo[2]=mul2(a1[2],i1); mo[3]=mul2(a1[3],i1);
    }
}

// ---------------- kB: BRA QKV GEMM (head-major out) + pooling ---------------
__global__ void kB_bra(const float* __restrict__ x, const float* __restrict__ w,
                       const float* __restrict__ bias) {
    extern __shared__ float sm[];
    float* s_xT  = sm;
    float* s_w   = sm + 64*68;
    float* s_qkv = s_w;
    int wid = blockIdx.x;
    int b = wid >> 8, r = wid & 255, ry = r >> 4, rx = r & 15;
    int tid = threadIdx.x;

    for (int i = tid; i < 4096; i += 256) {
        int t = i >> 6, c = i & 63;
        int y = ry*8 + (t >> 3), xx = rx*8 + (t & 7);
        s_xT[c*68 + t] = x[(((size_t)b*128 + y)*128 + xx)*128 + 64 + c];
    }
    for (int i = tid; i < 12288; i += 256) s_w[i] = w[i];
    __syncthreads();

    int t_m = tid & 15, t_n = tid >> 4;
    ull acc[4][6];
    #pragma unroll
    for (int i = 0; i < 4; i++)
        #pragma unroll
        for (int j = 0; j < 6; j++) acc[i][j] = 0ull;
    for (int k = 0; k < 64; k++) {
        float4 a4 = *(const float4*)(s_xT + k*68 + t_m*4);
        ull a0 = dup2(a4.x), a1 = dup2(a4.y), a2 = dup2(a4.z), a3 = dup2(a4.w);
        const ull* bp = (const ull*)(s_w + k*192 + t_n*12);
        ull b0=bp[0], b1=bp[1], b2=bp[2], b3=bp[3], b4=bp[4], b5=bp[5];
        acc[0][0]=fma2(a0,b0,acc[0][0]); acc[0][1]=fma2(a0,b1,acc[0][1]);
        acc[0][2]=fma2(a0,b2,acc[0][2]); acc[0][3]=fma2(a0,b3,acc[0][3]);
        acc[0][4]=fma2(a0,b4,acc[0][4]); acc[0][5]=fma2(a0,b5,acc[0][5]);
        acc[1][0]=fma2(a1,b0,acc[1][0]); acc[1][1]=fma2(a1,b1,acc[1][1]);
        acc[1][2]=fma2(a1,b2,acc[1][2]); acc[1][3]=fma2(a1,b3,acc[1][3]);
        acc[1][4]=fma2(a1,b4,acc[1][4]); acc[1][5]=fma2(a1,b5,acc[1][5]);
        acc[2][0]=fma2(a2,b0,acc[2][0]); acc[2][1]=fma2(a2,b1,acc[2][1]);
        acc[2][2]=fma2(a2,b2,acc[2][2]); acc[2][3]=fma2(a2,b3,acc[2][3]);
        acc[2][4]=fma2(a2,b4,acc[2][4]); acc[2][5]=fma2(a2,b5,acc[2][5]);
        acc[3][0]=fma2(a3,b0,acc[3][0]); acc[3][1]=fma2(a3,b1,acc[3][1]);
        acc[3][2]=fma2(a3,b2,acc[3][2]); acc[3][3]=fma2(a3,b3,acc[3][3]);
        acc[3][4]=fma2(a3,b4,acc[3][4]); acc[3][5]=fma2(a3,b5,acc[3][5]);
    }
    __syncthreads();
    {
        float bb[12];
        #pragma unroll
        for (int j = 0; j < 12; j++) bb[j] = __ldg(bias + t_n*12 + j);
        #pragma unroll
        for (int i = 0; i < 4; i++)
            #pragma unroll
            for (int j = 0; j < 6; j++) {
                float lo, hi; up2(acc[i][j], lo, hi);
                s_qkv[(t_m*4+i)*192 + t_n*12 + 2*j]     = lo + bb[2*j];
                s_qkv[(t_m*4+i)*192 + t_n*12 + 2*j + 1] = hi + bb[2*j+1];
            }
    }
    __syncthreads();

    for (int i = tid; i < 4096; i += 256) {
        int hh = i >> 9, rest = i & 511;
        int t = rest >> 3, d = rest & 7;
        size_t off = ((size_t)(b*8 + hh)*256 + r)*512 + rest;
        g_qb[off] = s_qkv[t*192 + hh*8 + d];
        g_kb[off] = s_qkv[t*192 + 64 + hh*8 + d];
        g_vb[off] = s_qkv[t*192 + 128 + hh*8 + d];
    }
    if (tid < 64) {
        float sq = 0.f, sk = 0.f;
        for (int t = 0; t < 64; t++) {
            sq += s_qkv[t*192 + tid];
            sk += s_qkv[t*192 + 64 + tid];
        }
        g_qr[wid*64 + tid] = sq * 0.015625f;
        g_kr[wid*64 + tid] = sk * 0.015625f;
    }
}

// ---------------- kC: routing + top-4 + accumulator zeroing -----------------
__global__ void kC_route() {
    __shared__ float s_q[64];
    __shared__ float s_a[256];
    int bx = blockIdx.x;
    int b = bx >> 8, i = bx & 255;
    int tid = threadIdx.x;
    if (bx < 32) g_gram[bx*256 + tid] = 0.f;
    else if (bx < 36) g_norm2[(bx-32)*256 + tid] = 0.f;
    if (tid < 64) s_q[tid] = g_qr[(b*256 + i)*64 + tid];
    __syncthreads();
    const float* kr = g_kr + (size_t)(b*256 + tid)*64;
    float a = 0.f;
    #pragma unroll 8
    for (int c = 0; c < 64; c++) a += s_q[c]*kr[c];
    s_a[tid] = a;
    __syncthreads();
    if (tid == 0) {
        for (int s = 0; s < 4; s++) {
            float best = -INFINITY; int bj = 0;
            for (int j = 0; j < 256; j++)
                if (s_a[j] > best) { best = s_a[j]; bj = j; }
            g_idx[(b*256 + i)*4 + s] = bj;
            s_a[bj] = -INFINITY;
        }
    }
}

// ---------------- kD: BRA gathered attention (2 heads/block) ----------------
__global__ void kD_attn() {
    __shared__ __align__(16) float s_k[2*256*8];
    __shared__ __align__(16) float s_v[2*256*8];
    __shared__ int s_i4[4];
    int bid = blockIdx.x;                     // 4096: b(4) x hp(4) x r(256)
    int b = bid >> 10, hp = (bid >> 8) & 3, r = bid & 255;
    int tid = threadIdx.x;                    // 128
    if (tid < 4) s_i4[tid] = g_idx[(b*256 + r)*4 + tid];
    __syncthreads();
    for (int i = tid; i < 1024; i += 128) {   // float4 units
        int hl = i >> 9, rem = i & 511;
        int key = rem >> 1, d4 = rem & 1;
        int reg = s_i4[key >> 6], t = key & 63;
        size_t off = ((size_t)(b*8 + hp*2 + hl)*256 + reg)*512 + t*8 + d4*4;
        *(float4*)(s_k + i*4) = *(const float4*)(g_kb + off);
        *(float4*)(s_v + i*4) = *(const float4*)(g_vb + off);
    }
    __syncthreads();
    int hl = tid >> 6, row = tid & 63;
    int h = hp*2 + hl;
    size_t qoff = ((size_t)(b*8 + h)*256 + r)*512 + row*8;
    const ull* qp = (const ull*)(g_qb + qoff);
    ull sc = dup2(SCALE);
    ull q0 = mul2(qp[0], sc), q1 = mul2(qp[1], sc),
        q2 = mul2(qp[2], sc), q3 = mul2(qp[3], sc);
    const ull* kb = (const ull*)s_k + hl*1024;
    const ull* vb = (const ull*)s_v + hl*1024;
    float ssum = 0.f;
    ull a0 = 0ull, a1 = 0ull, a2 = 0ull, a3 = 0ull;
    #pragma unroll 4
    for (int j = 0; j < 256; j++) {
        const ull* kp = kb + j*4;
        ull s2 = fma2(q0,kp[0], fma2(q1,kp[1], fma2(q2,kp[2], mul2(q3,kp[3]))));
        float e = __expf(hadd2(s2));
        ssum += e;
        ull ed = dup2(e);
        const ull* vp = vb + j*4;
        a0 = fma2(ed, vp[0], a0); a1 = fma2(ed, vp[1], a1);
        a2 = fma2(ed, vp[2], a2); a3 = fma2(ed, vp[3], a3);
    }
    ull inv = dup2(1.f/ssum);
    int y = (r >> 4)*8 + (row >> 3), xx = (r & 15)*8 + (row & 7);
    ull* mo = (ull*)(g_mid + ((size_t)b*LL + y*128 + xx)*128 + 64 + h*8);
    mo[0] = mul2(a0, inv); mo[1] = mul2(a1, inv);
    mo[2] = mul2(a2, inv); mo[3] = mul2(a3, inv);
}

// ---------------- kE: depthwise 3x3 LEPE ------------------------------------
__global__ void kE_lepe(const float* __restrict__ lw, const float* __restrict__ lb) {
    int pid = blockIdx.x*2 + (threadIdx.x >> 7);
    int b = pid >> 14, l = pid & 16383;
    int y = l >> 7, xx = l & 127;
    int c = threadIdx.x & 127;
    float acc = __ldg(lb + c);
    const float* wr = lw + c*9;
    #pragma unroll
    for (int ky = 0; ky < 3; ky++) {
        int yy = y + ky - 1;
        if (yy < 0 || yy >= 128) continue;
        #pragma unroll
        for (int kx = 0; kx < 3; kx++) {
            int xc = xx + kx - 1;
            if (xc < 0 || xc >= 128) continue;
            int rr = (yy >> 3)*16 + (xc >> 3), tt = (yy & 7)*8 + (xc & 7);
            float v;
            if (c < 64) {
                int hh = c >> 3, d = c & 7;
                v = g_vb[((size_t)(b*8 + hh)*256 + rr)*512 + tt*8 + d];
            } else {
                v = g_winv[((size_t)(b*256 + rr))*4096 + tt*64 + (c - 64)];
            }
            acc += v * __ldg(wr + ky*3 + kx);
        }
    }
    g_mid[((size_t)b*LL + l)*128 + c] += acc;
}

// ---------------- kF1: CA-qkv GEMM 65536x384x128 (token-major out) ----------
__global__ void kF1_caqkv(const float* __restrict__ w, const float* __restrict__ bias) {
    extern __shared__ float sm[];
    float* AsT = sm;          // 128 k x 68 m
    float* Bs  = sm + 8704;   // 128 k x 128 n
    float* Cs  = sm;          // reuse for epilogue (64 x 132)
    int m0 = blockIdx.x * 64;
    int nb = blockIdx.y;      // 0:q 1:k 2:v
    int tid = threadIdx.x;

    for (int i = tid; i < 8192; i += 256) {
        int t = i >> 7, k = i & 127;
        AsT[k*68 + t] = g_mid[(size_t)(m0 + t)*128 + k];
    }
    for (int i = tid; i < 16384; i += 256) {
        int k = i >> 7, n = i & 127;
        Bs[i] = w[k*384 + nb*128 + n];
    }
    __syncthreads();

    int t_m = tid & 15, t_n = tid >> 4;   // m = t_m*4, n = t_n*8
    ull acc[4][4];
    #pragma unroll
    for (int i = 0; i < 4; i++)
        #pragma unroll
        for (int j = 0; j < 4; j++) acc[i][j] = 0ull;
    #pragma unroll 4
    for (int k = 0; k < 128; k++) {
        float4 a4 = *(const float4*)(AsT + k*68 + t_m*4);
        ull a0 = dup2(a4.x), a1 = dup2(a4.y), a2 = dup2(a4.z), a3 = dup2(a4.w);
        const ull* bp = (const ull*)(Bs + k*128 + t_n*8);
        ull b0=bp[0], b1=bp[1], b2=bp[2], b3=bp[3];
        acc[0][0]=fma2(a0,b0,acc[0][0]); acc[0][1]=fma2(a0,b1,acc[0][1]);
        acc[0][2]=fma2(a0,b2,acc[0][2]); acc[0][3]=fma2(a0,b3,acc[0][3]);
        acc[1][0]=fma2(a1,b0,acc[1][0]); acc[1][1]=fma2(a1,b1,acc[1][1]);
        acc[1][2]=fma2(a1,b2,acc[1][2]); acc[1][3]=fma2(a1,b3,acc[1][3]);
        acc[2][0]=fma2(a2,b0,acc[2][0]); acc[2][1]=fma2(a2,b1,acc[2][1]);
        acc[2][2]=fma2(a2,b2,acc[2][2]); acc[2][3]=fma2(a2,b3,acc[2][3]);
        acc[3][0]=fma2(a3,b0,acc[3][0]); acc[3][1]=fma2(a3,b1,acc[3][1]);
        acc[3][2]=fma2(a3,b2,acc[3][2]); acc[3][3]=fma2(a3,b3,acc[3][3]);
    }
    __syncthreads();

    {
        float bb[8];
        #pragma unroll
        for (int j = 0; j < 8; j++) bb[j] = __ldg(bias + nb*128 + t_n*8 + j);
        #pragma unroll
        for (int i = 0; i < 4; i++)
            #pragma unroll
            for (int j = 0; j < 4; j++) {
                float lo, hi; up2(acc[i][j], lo, hi);
                Cs[(t_m*4+i)*132 + t_n*8 + 2*j]     = lo + bb[2*j];
                Cs[(t_m*4+i)*132 + t_n*8 + 2*j + 1] = hi + bb[2*j+1];
            }
    }
    __syncthreads();
    float* dst = (nb == 0) ? g_cq : (nb == 1) ? g_ck : g_cv;
    for (int i = tid; i < 2048; i += 256) {   // float4 units
        int m = i >> 5, nf = i & 31;
        *(float4*)(dst + (size_t)(m0 + m)*128 + nf*4) = *(const float4*)(Cs + m*132 + nf*4);
    }
}

// ---------------- kF23: fused norms + partial grams (token-major) -----------
__global__ void kF23() {
    extern __shared__ float sm[];
    float* qs = sm;           // 64 tokens x 128 ch
    float* ks = sm + 8192;
    int bid = blockIdx.x;     // 1024 = b(4) x chunk(256)
    int b = bid >> 8, ch = bid & 255;
    int l0 = ch*64;
    int tid = threadIdx.x;    // 256
    const float4* qsrc = (const float4*)(g_cq + ((size_t)b*LL + l0)*128);
    const float4* ksrc = (const float4*)(g_ck + ((size_t)b*LL + l0)*128);
    for (int i = tid; i < 2048; i += 256) {
        ((float4*)qs)[i] = qsrc[i];
        ((float4*)ks)[i] = ksrc[i];
    }
    __syncthreads();
    // norms: tid<128 -> q channel tid; tid>=128 -> k channel tid-128
    {
        const float* base = (tid < 128) ? (qs + tid) : (ks + (tid - 128));
        float ns = 0.f;
        #pragma unroll 8
        for (int t = 0; t < 64; t++) { float v = base[t*128]; ns += v*v; }
        atomicAdd(&g_norm2[((tid < 128) ? 0 : 512) + b*128 + (tid & 127)], ns);
    }
    // grams: tid -> (d = tid>>4, e = tid&15), loop heads
    int d = tid >> 4, e = tid & 15;
    #pragma unroll
    for (int h = 0; h < 8; h++) {
        const float* qp = qs + h*16 + d;
        const float* kp = ks + h*16 + e;
        float acc = 0.f;
        #pragma unroll 8
        for (int t = 0; t < 64; t++) acc += qp[t*128]*kp[t*128];
        atomicAdd(&g_gram[(b*8 + h)*256 + tid], acc);
    }
}

// ---------------- kF3b: normalize + softmax ----------------------------------
__global__ void kF3b(const float* __restrict__ temp) {
    __shared__ float smm[256];
    int bh = blockIdx.x;
    int b = bh >> 3, h = bh & 7;
    int tid = threadIdx.x;
    int d = tid >> 4, e = tid & 15;
    int rowq = b*128 + h*16;
    float nq = fmaxf(sqrtf(g_norm2[rowq + d]), 1e-12f);
    float nk = fmaxf(sqrtf(g_norm2[512 + rowq + e]), 1e-12f);
    smm[tid] = g_gram[bh*256 + tid] / (nq*nk) * __ldg(temp + h);
    __syncthreads();
    if (tid < 16) {
        float mx = -INFINITY;
        for (int j = 0; j < 16; j++) mx = fmaxf(mx, smm[tid*16 + j]);
        float ssum = 0.f, ex[16];
        for (int j = 0; j < 16; j++) { ex[j] = __expf(smm[tid*16 + j] - mx); ssum += ex[j]; }
        float inv = 1.f/ssum;
        for (int j = 0; j < 16; j++) g_attn[bh*256 + tid*16 + j] = ex[j]*inv;
    }
}

// ---------------- kF4: cout mix + 128x128 projection --------------------------
__global__ void kF4_out(const float* __restrict__ pw, const float* __restrict__ pb,
                        float* __restrict__ out) {
    extern __shared__ float sm[];
    float* s_attn = sm;           // 2048
    float* s_cv   = sm + 2048;    // 64 x 128
    float* coutT  = sm + 10240;   // 128 k x 68 m
    int tok0 = blockIdx.x * 64;
    int b = tok0 >> 14;
    int tid = threadIdx.x;        // 256
    for (int i = tid; i < 2048; i += 256) s_attn[i] = g_attn[b*2048 + i];
    for (int i = tid; i < 8192; i += 256) s_cv[i] = g_cv[(size_t)tok0*128 + i];
    __syncthreads();
    // cout[m][ch] = sum_e attn[ch*16+e] * cv[m][h*16+e]
    for (int i = tid; i < 8192; i += 256) {
        int m = i >> 7, chn = i & 127;
        int h = chn >> 4;
        const ull* ap  = (const ull*)(s_attn + chn*16);
        const ull* cvp = (const ull*)(s_cv + m*128 + h*16);
        ull acc = mul2(ap[0], cvp[0]);
        acc = fma2(ap[1], cvp[1], acc);
        acc = fma2(ap[2], cvp[2], acc);
        acc = fma2(ap[3], cvp[3], acc);
        acc = fma2(ap[4], cvp[4], acc);
        acc = fma2(ap[5], cvp[5], acc);
        acc = fma2(ap[6], cvp[6], acc);
        acc = fma2(ap[7], cvp[7], acc);
        coutT[chn*68 + m] = hadd2(acc);
    }
    __syncthreads();
    // projection 64m x 128n x 128k
    int t_m = tid & 15, t_n = tid >> 4;
    ull acc[4][4];
    #pragma unroll
    for (int i = 0; i < 4; i++)
        #pragma unroll
        for (int j = 0; j < 4; j++) acc[i][j] = 0ull;
    #pragma unroll 4
    for (int k = 0; k < 128; k++) {
        float4 a4 = *(const float4*)(coutT + k*68 + t_m*4);
        ull a0 = dup2(a4.x), a1 = dup2(a4.y), a2 = dup2(a4.z), a3 = dup2(a4.w);
        float4 w0 = __ldg((const float4*)(pw + k*128 + t_n*8));
        float4 w1 = __ldg((const float4*)(pw + k*128 + t_n*8 + 4));
        ull b0 = pk2(w0.x, w0.y), b1 = pk2(w0.z, w0.w);
        ull b2 = pk2(w1.x, w1.y), b3 = pk2(w1.z, w1.w);
        acc[0][0]=fma2(a0,b0,acc[0][0]); acc[0][1]=fma2(a0,b1,acc[0][1]);
        acc[0][2]=fma2(a0,b2,acc[0][2]); acc[0][3]=fma2(a0,b3,acc[0][3]);
        acc[1][0]=fma2(a1,b0,acc[1][0]); acc[1][1]=fma2(a1,b1,acc[1][1]);
        acc[1][2]=fma2(a1,b2,acc[1][2]); acc[1][3]=fma2(a1,b3,acc[1][3]);
        acc[2][0]=fma2(a2,b0,acc[2][0]); acc[2][1]=fma2(a2,b1,acc[2][1]);
        acc[2][2]=fma2(a2,b2,acc[2][2]); acc[2][3]=fma2(a2,b3,acc[2][3]);
        acc[3][0]=fma2(a3,b0,acc[3][0]); acc[3][1]=fma2(a3,b1,acc[3][1]);
        acc[3][2]=fma2(a3,b2,acc[3][2]); acc[3][3]=fma2(a3,b3,acc[3][3]);
    }
    float4 pb0 = __ldg((const float4*)(pb + t_n*8));
    float4 pb1 = __ldg((const float4*)(pb + t_n*8 + 4));
    float bb[8] = {pb0.x,pb0.y,pb0.z,pb0.w,pb1.x,pb1.y,pb1.z,pb1.w};
    #pragma unroll
    for (int i = 0; i < 4; i++) {
        float r[8];
        #pragma unroll
        for (int j = 0; j < 4; j++) {
            float lo, hi; up2(acc[i][j], lo, hi);
            r[2*j] = lo + bb[2*j]; r[2*j+1] = hi + bb[2*j+1];
        }
        float* op = out + ((size_t)tok0 + t_m*4 + i)*128 + t_n*8;
        *(float4*)op     = make_float4(r[0], r[1], r[2], r[3]);
        *(float4*)(op+4) = make_float4(r[4], r[5], r[6], r[7]);
    }
}

// ---------------- launch ------------------------------------------------------
extern "C" void kernel_launch(void* const* d_in, const int* in_sizes, int n_in,
                              void* d_out, int out_size) {
    const float* x         = (const float*)d_in[0];
    const float* wqkv_w    = (const float*)d_in[1];
    const float* wqkv_b    = (const float*)d_in[2];
    const float* bqkv_w    = (const float*)d_in[3];
    const float* bqkv_b    = (const float*)d_in[4];
    const float* lepe_w    = (const float*)d_in[5];
    const float* lepe_b    = (const float*)d_in[6];
    const float* ca_qkv_w  = (const float*)d_in[7];
    const float* ca_qkv_b  = (const float*)d_in[8];
    const float* ca_temp   = (const float*)d_in[9];
    const float* ca_proj_w = (const float*)d_in[10];
    const float* ca_proj_b = (const float*)d_in[11];
    float* out = (float*)d_out;

    static bool attr_done = false;
    if (!attr_done) {
        cudaFuncSetAttribute(kA_win,   cudaFuncAttributeMaxDynamicSharedMemorySize, 66560);
        cudaFuncSetAttribute(kB_bra,   cudaFuncAttributeMaxDynamicSharedMemorySize, 66560);
        cudaFuncSetAttribute(kF1_caqkv,cudaFuncAttributeMaxDynamicSharedMemorySize, 100352);
        cudaFuncSetAttribute(kF23,     cudaFuncAttributeMaxDynamicSharedMemorySize, 65536);
        cudaFuncSetAttribute(kF4_out,  cudaFuncAttributeMaxDynamicSharedMemorySize, 75776);
        attr_done = true;
    }

    kA_win   <<<1024, 256, 66560>>>(x, wqkv_w, wqkv_b);
    kB_bra   <<<1024, 256, 66560>>>(x, bqkv_w, bqkv_b);
    kC_route <<<1024, 256>>>();
    kD_attn  <<<4096, 128>>>();
    kE_lepe  <<<32768, 256>>>(lepe_w, lepe_b);
    kF1_caqkv<<<dim3(1024, 3), 256, 100352>>>(ca_qkv_w, ca_qkv_b);
    kF23     <<<1024, 256, 65536>>>();
    kF3b     <<<32, 256>>>(ca_temp);
    kF4_out  <<<1024, 256, 75776>>>(ca_proj_w, ca_proj_b, out);
}